// round 12
// baseline (speedup 1.0000x reference)
#include <cuda_runtime.h>
#include <math.h>

#define H_   2048
#define HQ_  16
#define HKV_ 8
#define DH_  128
#define CHUNK_ 256
#define MAXCH_ 128
#define SCALE_ 0.08838834764831845f   // 1/sqrt(128)
#define EPS_ 1e-6f

// ------------------------- scratch (device globals, no allocs) --------------
__device__ float g_proj[4096];                 // raw q(2048) | k(1024) | v(1024)
__device__ float g_q[HQ_*DH_];                 // normed+roped q
__device__ float g_k[HKV_*DH_];                // normed+roped k_new
__device__ float g_v[HKV_*DH_];                // v_new
__device__ float g_m[HQ_*MAXCH_];
__device__ float g_l[HQ_*MAXCH_];
__device__ float g_acc[HQ_*MAXCH_*DH_];
__device__ float g_attn[HQ_*DH_];              // attention out, head-major

__device__ __forceinline__ float warpSum(float v) {
    #pragma unroll
    for (int o = 16; o; o >>= 1) v += __shfl_xor_sync(0xffffffffu, v, o);
    return v;
}
__device__ __forceinline__ float warpMax(float v) {
    #pragma unroll
    for (int o = 16; o; o >>= 1) v = fmaxf(v, __shfl_xor_sync(0xffffffffu, v, o));
    return v;
}

__device__ __forceinline__ float blockSum256(float v, float* red, int t) {
    float ws = warpSum(v);
    if ((t & 31) == 0) red[t >> 5] = ws;
    __syncthreads();
    float r = (t < 8) ? red[t] : 0.f;
    r = warpSum(r);
    if (t == 0) red[8] = r;
    __syncthreads();
    float out = red[8];
    __syncthreads();
    return out;
}
__device__ __forceinline__ float blockMax256(float v, float* red, int t) {
    float ws = warpMax(v);
    if ((t & 31) == 0) red[t >> 5] = ws;
    __syncthreads();
    float r = (t < 8) ? red[t] : -INFINITY;
    r = warpMax(r);
    if (t == 0) red[8] = r;
    __syncthreads();
    float out = red[8];
    __syncthreads();
    return out;
}

// ------------------------- 1: QKV projection (R2 shape) ----------------------
__global__ void k_proj(const float* __restrict__ x,
                       const float* __restrict__ Wq,
                       const float* __restrict__ Wk,
                       const float* __restrict__ Wv) {
    int e = blockIdx.x;
    const float* W = (e < 2048) ? (Wq + (size_t)e * H_)
                   : (e < 3072) ? (Wk + (size_t)(e - 2048) * H_)
                                : (Wv + (size_t)(e - 3072) * H_);
    int t = threadIdx.x;
    const float4* W4 = (const float4*)W;
    const float4* x4 = (const float4*)x;
    float acc = 0.f;
    #pragma unroll
    for (int k = 0; k < 4; k++) {
        float4 w  = W4[t + k * 128];
        float4 xv = x4[t + k * 128];
        acc += w.x * xv.x + w.y * xv.y + w.z * xv.z + w.w * xv.w;
    }
    __shared__ float s[4];
    float ws = warpSum(acc);
    if ((t & 31) == 0) s[t >> 5] = ws;
    __syncthreads();
    if (t == 0) g_proj[e] = s[0] + s[1] + s[2] + s[3];
}

// ------------------------- 2: RMSNorm + RoPE + copies (R2) -------------------
__global__ void k_norm_rope(const float* __restrict__ cosv,
                            const float* __restrict__ sinv,
                            const float* __restrict__ qw,
                            const float* __restrict__ kw,
                            float* __restrict__ out) {
    int b = blockIdx.x, t = threadIdx.x;
    const float* row = g_proj + b * DH_;
    if (b < 24) {
        bool isq = (b < 16);
        __shared__ float sx[DH_];
        __shared__ float red[8];
        float x = row[t];
        float ws = warpSum(x * x);
        if ((t & 31) == 0) red[t >> 5] = ws;
        __syncthreads();
        float ssum = red[0] + red[1] + red[2] + red[3];
        float rms = sqrtf(ssum * (1.0f / DH_) + EPS_);
        float xn = x / rms * (isq ? qw[t] : kw[t]);
        sx[t] = xn;
        __syncthreads();
        float rot = (t < 64) ? -sx[t + 64] : sx[t - 64];
        float o = xn * cosv[t] + rot * sinv[t];
        if (isq) {
            g_q[b * DH_ + t] = o;
        } else {
            int kv = b - 16;
            g_k[kv * DH_ + t] = o;
            out[2048 + kv * DH_ + t] = o;   // k_new output
        }
    } else {
        int kv = b - 24;
        float v = row[t];
        g_v[kv * DH_ + t] = v;
        out[3072 + kv * DH_ + t] = v;       // v output
    }
}

// ------------------------- 3: attention partials (max occupancy) -------------
// grid (nchunks, HKV) x 256 threads. launch_bounds(256,8) -> regs<=32,
// 64 warps/SM. __ldcs keeps the 134MB kc/vc stream evict-first (weights
// stay L2-resident across replays). __expf trims transient regs.
__global__ void __launch_bounds__(256, 8) k_attn_partial(
                               const float* __restrict__ kc,
                               const float* __restrict__ vc,
                               const float* __restrict__ mask,
                               int C) {
    int chunk = blockIdx.x;
    int kv = blockIdx.y;
    int t = threadIdx.x;
    int c = chunk * CHUNK_ + t;
    bool valid = (c < C);

    __shared__ float q0s[DH_], q1s[DH_];
    __shared__ float p0s[CHUNK_], p1s[CHUNK_];
    __shared__ float red[16];
    __shared__ float vred[CHUNK_];

    if (t < DH_) {
        q0s[t] = g_q[(kv * 2) * DH_ + t];
        q1s[t] = g_q[(kv * 2 + 1) * DH_ + t];
    }
    __syncthreads();

    float a0 = 0.f, a1 = 0.f;
    if (valid) {
        const float* kbase = kc + (size_t)kv * DH_ * C + c;
        #pragma unroll 16
        for (int d = 0; d < DH_; d++) {
            float kval = __ldcs(kbase + (size_t)d * C);
            a0 += q0s[d] * kval;
            a1 += q1s[d] * kval;
        }
    }
    float mval = valid ? mask[c] : 0.f;
    float s0 = valid ? (a0 * SCALE_ + mval) : -INFINITY;
    float s1 = valid ? (a1 * SCALE_ + mval) : -INFINITY;

    float m0 = blockMax256(s0, red, t);
    float m1 = blockMax256(s1, red, t);
    float p0 = valid ? __expf(s0 - m0) : 0.f;
    float p1 = valid ? __expf(s1 - m1) : 0.f;
    float l0 = blockSum256(p0, red, t);
    float l1 = blockSum256(p1, red, t);
    p0s[t] = p0; p1s[t] = p1;
    __syncthreads();

    // V accumulation: thread t handles dim (t&127), positions (t>>7), step 2.
    int d = t & 127;
    int half = t >> 7;
    const float* vbase = vc + (size_t)kv * C * DH_ + (size_t)(chunk * CHUNK_) * DH_ + d;
    float va0 = 0.f, va1 = 0.f;
    int cmax = C - chunk * CHUNK_;
    if (cmax > CHUNK_) cmax = CHUNK_;
    #pragma unroll 8
    for (int cc = half; cc < cmax; cc += 2) {
        float vv = __ldcs(vbase + (size_t)cc * DH_);
        va0 += p0s[cc] * vv;
        va1 += p1s[cc] * vv;
    }
    vred[t] = va0; __syncthreads();
    float tot0 = (t < 128) ? (vred[t] + vred[t + 128]) : 0.f;
    __syncthreads();
    vred[t] = va1; __syncthreads();
    float tot1 = (t < 128) ? (vred[t] + vred[t + 128]) : 0.f;

    int idx0 = (kv * 2) * MAXCH_ + chunk;
    int idx1 = (kv * 2 + 1) * MAXCH_ + chunk;
    if (t == 0) { g_m[idx0] = m0; g_l[idx0] = l0; g_m[idx1] = m1; g_l[idx1] = l1; }
    if (t < 128) {
        g_acc[(size_t)idx0 * DH_ + t] = tot0;
        g_acc[(size_t)idx1 * DH_ + t] = tot1;
    }
}

// ------------------------- 4: combine partials + new token (R2) --------------
__global__ void __launch_bounds__(512) k_attn_reduce(
                              const float* __restrict__ mask,
                              int C, int nchunks) {
    int qh = blockIdx.x, t = threadIdx.x;
    int kv = qh >> 1;
    __shared__ float sm[MAXCH_], sl[MAXCH_], sw[MAXCH_];
    __shared__ float red[8];
    __shared__ float sMax, sSnew, sL;
    __shared__ float vacc[512];

    if (t < nchunks) { sm[t] = g_m[qh * MAXCH_ + t]; sl[t] = g_l[qh * MAXCH_ + t]; }

    if (t < 128) {
        float prod = g_q[qh * DH_ + t] * g_k[kv * DH_ + t];
        float ws = warpSum(prod);
        if ((t & 31) == 0) red[t >> 5] = ws;
    }
    __syncthreads();
    if (t == 0) {
        float dot = red[0] + red[1] + red[2] + red[3];
        float s_new = dot * SCALE_ + mask[C];
        float M = s_new;
        for (int j = 0; j < nchunks; j++) M = fmaxf(M, sm[j]);
        sMax = M;
        sSnew = s_new;
    }
    __syncthreads();
    float M = sMax;
    if (t < nchunks) sw[t] = expf(sm[t] - M);
    __syncthreads();
    if (t < 64) {
        float lv = 0.f;
        for (int j = t; j < nchunks; j += 64) lv += sw[j] * sl[j];
        float ws = warpSum(lv);
        if (t == 0) red[0] = ws;
        if (t == 32) red[1] = ws;
    }
    __syncthreads();
    if (t == 0) sL = expf(sSnew - M) + red[0] + red[1];
    __syncthreads();

    int d = t & 127;
    int cg = t >> 7;
    const float* accb = g_acc + (size_t)qh * MAXCH_ * DH_ + d;
    float a = 0.f;
    #pragma unroll 8
    for (int j = cg; j < nchunks; j += 4)
        a += sw[j] * accb[(size_t)j * DH_];
    vacc[t] = a;
    __syncthreads();
    if (t < 128) {
        float wnew = expf(sSnew - M);
        float tot = vacc[t] + vacc[t + 128] + vacc[t + 256] + vacc[t + 384]
                  + wnew * g_v[kv * DH_ + t];
        g_attn[qh * DH_ + t] = tot / sL;
    }
}

// ------------------------- 5: o_proj (R2 shape) ------------------------------
__global__ void k_oproj(const float* __restrict__ Wo, float* __restrict__ out) {
    int i = blockIdx.x, t = threadIdx.x;
    const float4* W4 = (const float4*)(Wo + (size_t)i * (HQ_ * DH_));
    const float4* a4 = (const float4*)g_attn;
    float acc = 0.f;
    #pragma unroll
    for (int k = 0; k < 4; k++) {
        float4 w = W4[t + k * 128];
        float4 a = a4[t + k * 128];
        acc += w.x * a.x + w.y * a.y + w.z * a.z + w.w * a.w;
    }
    __shared__ float s[4];
    float ws = warpSum(acc);
    if ((t & 31) == 0) s[t >> 5] = ws;
    __syncthreads();
    if (t == 0) out[i] = s[0] + s[1] + s[2] + s[3];
}

// ------------------------- launch --------------------------------------------
extern "C" void kernel_launch(void* const* d_in, const int* in_sizes, int n_in,
                              void* d_out, int out_size) {
    const float* x     = (const float*)d_in[0];
    const float* cosv  = (const float*)d_in[1];
    const float* sinv  = (const float*)d_in[2];
    const float* mask  = (const float*)d_in[3];
    const float* kc    = (const float*)d_in[4];
    const float* vc    = (const float*)d_in[5];
    const float* Wq    = (const float*)d_in[6];
    const float* Wk    = (const float*)d_in[7];
    const float* Wv    = (const float*)d_in[8];
    const float* Wo    = (const float*)d_in[9];
    const float* qw    = (const float*)d_in[10];
    const float* kw    = (const float*)d_in[11];
    float* out = (float*)d_out;

    int C = in_sizes[4] / (HKV_ * DH_);           // 16384
    int nchunks = (C + CHUNK_ - 1) / CHUNK_;      // 64
    if (nchunks > MAXCH_) nchunks = MAXCH_;

    k_proj<<<4096, 128>>>(x, Wq, Wk, Wv);
    k_norm_rope<<<32, 128>>>(cosv, sinv, qw, kw, out);
    dim3 g3(nchunks, HKV_);
    k_attn_partial<<<g3, 256>>>(kc, vc, mask, C);
    k_attn_reduce<<<HQ_, 512>>>(mask, C, nchunks);
    k_oproj<<<2048, 128>>>(Wo, out);
}

// round 13
// speedup vs baseline: 1.0576x; 1.0576x over previous
#include <cuda_runtime.h>
#include <math.h>

#define H_   2048
#define HQ_  16
#define HKV_ 8
#define DH_  128
#define CHUNK_ 256
#define MAXCH_ 128
#define SCALE_ 0.08838834764831845f   // 1/sqrt(128)
#define EPS_ 1e-6f

// ------------------------- scratch (device globals, no allocs) --------------
__device__ float g_proj[4096];                 // raw q(2048) | k(1024) | v(1024)
__device__ float g_q[HQ_*DH_];                 // normed+roped q
__device__ float g_k[HKV_*DH_];                // normed+roped k_new
__device__ float g_v[HKV_*DH_];                // v_new
__device__ float g_m[HQ_*MAXCH_];
__device__ float g_l[HQ_*MAXCH_];
__device__ float g_acc[HQ_*MAXCH_*DH_];
__device__ float g_attn[HQ_*DH_];              // attention out, head-major

__device__ __forceinline__ float warpSum(float v) {
    #pragma unroll
    for (int o = 16; o; o >>= 1) v += __shfl_xor_sync(0xffffffffu, v, o);
    return v;
}
__device__ __forceinline__ float warpMax(float v) {
    #pragma unroll
    for (int o = 16; o; o >>= 1) v = fmaxf(v, __shfl_xor_sync(0xffffffffu, v, o));
    return v;
}

__device__ __forceinline__ float blockSum256(float v, float* red, int t) {
    float ws = warpSum(v);
    if ((t & 31) == 0) red[t >> 5] = ws;
    __syncthreads();
    float r = (t < 8) ? red[t] : 0.f;
    r = warpSum(r);
    if (t == 0) red[8] = r;
    __syncthreads();
    float out = red[8];
    __syncthreads();
    return out;
}
__device__ __forceinline__ float blockMax256(float v, float* red, int t) {
    float ws = warpMax(v);
    if ((t & 31) == 0) red[t >> 5] = ws;
    __syncthreads();
    float r = (t < 8) ? red[t] : -INFINITY;
    r = warpMax(r);
    if (t == 0) red[8] = r;
    __syncthreads();
    float out = red[8];
    __syncthreads();
    return out;
}

// ------------------------- 1: QKV projection (occupancy-capped) --------------
__global__ void __launch_bounds__(128, 16) k_proj(
                       const float* __restrict__ x,
                       const float* __restrict__ Wq,
                       const float* __restrict__ Wk,
                       const float* __restrict__ Wv) {
    int e = blockIdx.x;
    const float* W = (e < 2048) ? (Wq + (size_t)e * H_)
                   : (e < 3072) ? (Wk + (size_t)(e - 2048) * H_)
                                : (Wv + (size_t)(e - 3072) * H_);
    int t = threadIdx.x;
    const float4* W4 = (const float4*)W;
    const float4* x4 = (const float4*)x;
    float acc = 0.f;
    #pragma unroll
    for (int k = 0; k < 4; k++) {
        float4 w  = W4[t + k * 128];
        float4 xv = x4[t + k * 128];
        acc += w.x * xv.x + w.y * xv.y + w.z * xv.z + w.w * xv.w;
    }
    __shared__ float s[4];
    float ws = warpSum(acc);
    if ((t & 31) == 0) s[t >> 5] = ws;
    __syncthreads();
    if (t == 0) g_proj[e] = s[0] + s[1] + s[2] + s[3];
}

// ------------------------- 2: RMSNorm + RoPE + copies (R2) -------------------
__global__ void k_norm_rope(const float* __restrict__ cosv,
                            const float* __restrict__ sinv,
                            const float* __restrict__ qw,
                            const float* __restrict__ kw,
                            float* __restrict__ out) {
    int b = blockIdx.x, t = threadIdx.x;
    const float* row = g_proj + b * DH_;
    if (b < 24) {
        bool isq = (b < 16);
        __shared__ float sx[DH_];
        __shared__ float red[8];
        float x = row[t];
        float ws = warpSum(x * x);
        if ((t & 31) == 0) red[t >> 5] = ws;
        __syncthreads();
        float ssum = red[0] + red[1] + red[2] + red[3];
        float rms = sqrtf(ssum * (1.0f / DH_) + EPS_);
        float xn = x / rms * (isq ? qw[t] : kw[t]);
        sx[t] = xn;
        __syncthreads();
        float rot = (t < 64) ? -sx[t + 64] : sx[t - 64];
        float o = xn * cosv[t] + rot * sinv[t];
        if (isq) {
            g_q[b * DH_ + t] = o;
        } else {
            int kv = b - 16;
            g_k[kv * DH_ + t] = o;
            out[2048 + kv * DH_ + t] = o;   // k_new output
        }
    } else {
        int kv = b - 24;
        float v = row[t];
        g_v[kv * DH_ + t] = v;
        out[3072 + kv * DH_ + t] = v;       // v output
    }
}

// ------------------------- 3: attention partials (R11 exact) -----------------
// grid (nchunks, HKV) x 256 threads. launch_bounds(256,6): ~48 warps/SM.
// __ldcs keeps the 134MB kc/vc stream evict-first.
__global__ void __launch_bounds__(256, 6) k_attn_partial(
                               const float* __restrict__ kc,
                               const float* __restrict__ vc,
                               const float* __restrict__ mask,
                               int C) {
    int chunk = blockIdx.x;
    int kv = blockIdx.y;
    int t = threadIdx.x;
    int c = chunk * CHUNK_ + t;
    bool valid = (c < C);

    __shared__ float q0s[DH_], q1s[DH_];
    __shared__ float p0s[CHUNK_], p1s[CHUNK_];
    __shared__ float red[16];
    __shared__ float vred[CHUNK_];

    if (t < DH_) {
        q0s[t] = g_q[(kv * 2) * DH_ + t];
        q1s[t] = g_q[(kv * 2 + 1) * DH_ + t];
    }
    __syncthreads();

    float a0 = 0.f, a1 = 0.f;
    if (valid) {
        const float* kbase = kc + (size_t)kv * DH_ * C + c;
        #pragma unroll 16
        for (int d = 0; d < DH_; d++) {
            float kval = __ldcs(kbase + (size_t)d * C);
            a0 += q0s[d] * kval;
            a1 += q1s[d] * kval;
        }
    }
    float mval = valid ? mask[c] : 0.f;
    float s0 = valid ? (a0 * SCALE_ + mval) : -INFINITY;
    float s1 = valid ? (a1 * SCALE_ + mval) : -INFINITY;

    float m0 = blockMax256(s0, red, t);
    float m1 = blockMax256(s1, red, t);
    float p0 = valid ? expf(s0 - m0) : 0.f;
    float p1 = valid ? expf(s1 - m1) : 0.f;
    float l0 = blockSum256(p0, red, t);
    float l1 = blockSum256(p1, red, t);
    p0s[t] = p0; p1s[t] = p1;
    __syncthreads();

    // V accumulation: thread t handles dim (t&127), positions (t>>7), step 2.
    int d = t & 127;
    int half = t >> 7;
    const float* vbase = vc + (size_t)kv * C * DH_ + (size_t)(chunk * CHUNK_) * DH_ + d;
    float va0 = 0.f, va1 = 0.f;
    int cmax = C - chunk * CHUNK_;
    if (cmax > CHUNK_) cmax = CHUNK_;
    #pragma unroll 8
    for (int cc = half; cc < cmax; cc += 2) {
        float vv = __ldcs(vbase + (size_t)cc * DH_);
        va0 += p0s[cc] * vv;
        va1 += p1s[cc] * vv;
    }
    vred[t] = va0; __syncthreads();
    float tot0 = (t < 128) ? (vred[t] + vred[t + 128]) : 0.f;
    __syncthreads();
    vred[t] = va1; __syncthreads();
    float tot1 = (t < 128) ? (vred[t] + vred[t + 128]) : 0.f;

    int idx0 = (kv * 2) * MAXCH_ + chunk;
    int idx1 = (kv * 2 + 1) * MAXCH_ + chunk;
    if (t == 0) { g_m[idx0] = m0; g_l[idx0] = l0; g_m[idx1] = m1; g_l[idx1] = l1; }
    if (t < 128) {
        g_acc[(size_t)idx0 * DH_ + t] = tot0;
        g_acc[(size_t)idx1 * DH_ + t] = tot1;
    }
}

// ------------------------- 4: combine partials + new token (R2) --------------
__global__ void __launch_bounds__(512) k_attn_reduce(
                              const float* __restrict__ mask,
                              int C, int nchunks) {
    int qh = blockIdx.x, t = threadIdx.x;
    int kv = qh >> 1;
    __shared__ float sm[MAXCH_], sl[MAXCH_], sw[MAXCH_];
    __shared__ float red[8];
    __shared__ float sMax, sSnew, sL;
    __shared__ float vacc[512];

    if (t < nchunks) { sm[t] = g_m[qh * MAXCH_ + t]; sl[t] = g_l[qh * MAXCH_ + t]; }

    if (t < 128) {
        float prod = g_q[qh * DH_ + t] * g_k[kv * DH_ + t];
        float ws = warpSum(prod);
        if ((t & 31) == 0) red[t >> 5] = ws;
    }
    __syncthreads();
    if (t == 0) {
        float dot = red[0] + red[1] + red[2] + red[3];
        float s_new = dot * SCALE_ + mask[C];
        float M = s_new;
        for (int j = 0; j < nchunks; j++) M = fmaxf(M, sm[j]);
        sMax = M;
        sSnew = s_new;
    }
    __syncthreads();
    float M = sMax;
    if (t < nchunks) sw[t] = expf(sm[t] - M);
    __syncthreads();
    if (t < 64) {
        float lv = 0.f;
        for (int j = t; j < nchunks; j += 64) lv += sw[j] * sl[j];
        float ws = warpSum(lv);
        if (t == 0) red[0] = ws;
        if (t == 32) red[1] = ws;
    }
    __syncthreads();
    if (t == 0) sL = expf(sSnew - M) + red[0] + red[1];
    __syncthreads();

    int d = t & 127;
    int cg = t >> 7;
    const float* accb = g_acc + (size_t)qh * MAXCH_ * DH_ + d;
    float a = 0.f;
    #pragma unroll 8
    for (int j = cg; j < nchunks; j += 4)
        a += sw[j] * accb[(size_t)j * DH_];
    vacc[t] = a;
    __syncthreads();
    if (t < 128) {
        float wnew = expf(sSnew - M);
        float tot = vacc[t] + vacc[t + 128] + vacc[t + 256] + vacc[t + 384]
                  + wnew * g_v[kv * DH_ + t];
        g_attn[qh * DH_ + t] = tot / sL;
    }
}

// ------------------------- 5: o_proj (occupancy-capped) ----------------------
__global__ void __launch_bounds__(128, 16) k_oproj(
                       const float* __restrict__ Wo, float* __restrict__ out) {
    int i = blockIdx.x, t = threadIdx.x;
    const float4* W4 = (const float4*)(Wo + (size_t)i * (HQ_ * DH_));
    const float4* a4 = (const float4*)g_attn;
    float acc = 0.f;
    #pragma unroll
    for (int k = 0; k < 4; k++) {
        float4 w = W4[t + k * 128];
        float4 a = a4[t + k * 128];
        acc += w.x * a.x + w.y * a.y + w.z * a.z + w.w * a.w;
    }
    __shared__ float s[4];
    float ws = warpSum(acc);
    if ((t & 31) == 0) s[t >> 5] = ws;
    __syncthreads();
    if (t == 0) out[i] = s[0] + s[1] + s[2] + s[3];
}

// ------------------------- launch --------------------------------------------
extern "C" void kernel_launch(void* const* d_in, const int* in_sizes, int n_in,
                              void* d_out, int out_size) {
    const float* x     = (const float*)d_in[0];
    const float* cosv  = (const float*)d_in[1];
    const float* sinv  = (const float*)d_in[2];
    const float* mask  = (const float*)d_in[3];
    const float* kc    = (const float*)d_in[4];
    const float* vc    = (const float*)d_in[5];
    const float* Wq    = (const float*)d_in[6];
    const float* Wk    = (const float*)d_in[7];
    const float* Wv    = (const float*)d_in[8];
    const float* Wo    = (const float*)d_in[9];
    const float* qw    = (const float*)d_in[10];
    const float* kw    = (const float*)d_in[11];
    float* out = (float*)d_out;

    int C = in_sizes[4] / (HKV_ * DH_);           // 16384
    int nchunks = (C + CHUNK_ - 1) / CHUNK_;      // 64
    if (nchunks > MAXCH_) nchunks = MAXCH_;

    k_proj<<<4096, 128>>>(x, Wq, Wk, Wv);
    k_norm_rope<<<32, 128>>>(cosv, sinv, qw, kw, out);
    dim3 g3(nchunks, HKV_);
    k_attn_partial<<<g3, 256>>>(kc, vc, mask, C);
    k_attn_reduce<<<HQ_, 512>>>(mask, C, nchunks);
    k_oproj<<<2048, 128>>>(Wo, out);
}